// round 9
// baseline (speedup 1.0000x reference)
#include <cuda_runtime.h>
#include <cstdint>

// Problem dims (fixed by the reference)
#define NB   4
#define NN   2048
#define FIN  128
#define NH   4
#define NC   32
#define HC   128            // NH*NC
#define ROWS (NB*NN)        // 8192 flattened (b,n)
#define MAXD 128            // neighbor-list capacity per row (avg degree ~21.5)
#define NEG  0.2f
#define GEMMB (ROWS/8)      // 1024 gemm blocks (8 nodes each)

// -------- device scratch (no allocations allowed) --------
__device__ float          g_feat [ROWS*HC];       // x@W (4MB)
__device__ float          g_s    [ROWS*NH];       // a_src logits
__device__ float          g_d    [ROWS*NH];       // a_dst logits
__device__ float          g_denom[ROWS*NH];       // column softmax denominators
__device__ float          g_w    [ROWS*MAXD*NH];  // per-edge exp numerators
__device__ unsigned short g_nbr  [ROWS*MAXD];     // per-row neighbor indices
__device__ int            g_cnt  [ROWS];          // per-row neighbor counts

// packed f32x2 FMA (Blackwell; ptxas never emits it, PTX-only)
__device__ __forceinline__ unsigned long long ffma2(
        unsigned long long a, unsigned long long b, unsigned long long c) {
    unsigned long long d;
    asm("fma.rn.f32x2 %0, %1, %2, %3;" : "=l"(d) : "l"(a), "l"(b), "l"(c));
    return d;
}

// -------- K1: FUSED, INTERLEAVED 1:8  (bx%9==0 -> gemm, else adj-row scan) --------
// Interleaving puts the 1:8 gemm:scan mix in EVERY wave, so the FFMA-bound GEMM
// and DRAM-bound scan are co-resident (front-packed grids ran the phases serially).
__global__ void __launch_bounds__(128) k_front(
        const float*  __restrict__ x,    const float* __restrict__ W,
        const float*  __restrict__ asrc, const float* __restrict__ adst,
        const float4* __restrict__ adj4) {
    const int t  = threadIdx.x;
    const int bx = blockIdx.x;

    if (bx % 9 == 0) {
        // ---------------- GEMM: 8 nodes/block, thread t = output column ----------------
        const int g  = bx / 9;              // 0..GEMMB-1
        const int n0 = g * 8;
        __shared__ __align__(16) float xs[FIN*8];   // [k][m], 4KB

        // fused: zero softmax denominators (first 256 gemm blocks cover 32K floats)
        {
            int z = g * 128 + t;
            if (z < ROWS*NH) g_denom[z] = 0.0f;
        }

        for (int idx = t; idx < 8*FIN; idx += 128) {
            int m = idx >> 7, k = idx & 127;
            xs[k*8 + m] = x[(size_t)(n0 + m)*FIN + k];
        }
        __syncthreads();

        // packed f32x2 mainloop: per k = 1 LDG + 1 pack + 2 LDS.128 + 4 FFMA2
        unsigned long long acc2[4] = {0ull, 0ull, 0ull, 0ull};
        const ulonglong2* xv2 = (const ulonglong2*)xs;
#pragma unroll 8
        for (int k = 0; k < FIN; k++) {
            float wv = __ldg(&W[(size_t)k*HC + t]);
            unsigned long long wv2;
            asm("mov.b64 %0, {%1, %1};" : "=l"(wv2) : "r"(__float_as_uint(wv)));
            ulonglong2 p0 = xv2[k*2+0];     // m0..3 (broadcast LDS.128)
            ulonglong2 p1 = xv2[k*2+1];     // m4..7
            acc2[0] = ffma2(p0.x, wv2, acc2[0]);
            acc2[1] = ffma2(p0.y, wv2, acc2[1]);
            acc2[2] = ffma2(p1.x, wv2, acc2[2]);
            acc2[3] = ffma2(p1.y, wv2, acc2[3]);
        }

        float am[8];
#pragma unroll
        for (int p = 0; p < 4; p++) {
            unsigned int lo, hi;
            asm("mov.b64 {%0, %1}, %2;" : "=r"(lo), "=r"(hi) : "l"(acc2[p]));
            am[2*p+0] = __uint_as_float(lo);
            am[2*p+1] = __uint_as_float(hi);
        }

#pragma unroll
        for (int m = 0; m < 8; m++)
            g_feat[(size_t)(n0+m)*HC + t] = am[m];

        // fused attention logits: warp == head h, lane == channel c
        const int h = t >> 5, lane = t & 31;
        const float as = asrc[h*NC + lane];
        const float ad = adst[h*NC + lane];
#pragma unroll
        for (int m = 0; m < 8; m++) {
            float vs = am[m] * as;
            float vd = am[m] * ad;
#pragma unroll
            for (int o = 16; o; o >>= 1) {
                vs += __shfl_xor_sync(0xffffffffu, vs, o);
                vd += __shfl_xor_sync(0xffffffffu, vd, o);
            }
            if (lane == 0) {
                g_s[(n0 + m)*NH + h] = vs;
                g_d[(n0 + m)*NH + h] = vd;
            }
        }
    } else {
        // ---------------- SCAN: one adj row/block, 4 batched LDG.128 per thread ----------------
        __shared__ int cnt_s;
        __shared__ unsigned short list_s[MAXD];
        const int row = bx - bx/9 - 1;      // de-interleaved row id, 0..ROWS-1
        const int i   = row & (NN - 1);

        if (t == 0) cnt_s = 0;

        const float4* base = adj4 + (size_t)row * (NN/4);
        float4 v0 = base[t      ];
        float4 v1 = base[t + 128];
        float4 v2 = base[t + 256];
        float4 v3 = base[t + 384];
        __syncthreads();

        float vals[16] = {v0.x,v0.y,v0.z,v0.w, v1.x,v1.y,v1.z,v1.w,
                          v2.x,v2.y,v2.z,v2.w, v3.x,v3.y,v3.z,v3.w};
#pragma unroll
        for (int u = 0; u < 4; u++) {
#pragma unroll
            for (int c = 0; c < 4; c++) {
                int j = (t + u*128)*4 + c;
                if (vals[u*4+c] != 0.0f || j == i) {   // self-loop always present
                    int p = atomicAdd(&cnt_s, 1);
                    if (p < MAXD) list_s[p] = (unsigned short)j;
                }
            }
        }
        __syncthreads();

        const int cnt = min(cnt_s, MAXD);
        if (t == 0) g_cnt[row] = cnt;
        if (t < cnt) g_nbr[(size_t)row*MAXD + t] = list_s[t];
    }
}

// -------- K2: column softmax denominators + stash per-edge exp numerators --------
__global__ void __launch_bounds__(256) k_denom() {
    const int warp = threadIdx.x >> 5, lane = threadIdx.x & 31;
    const int row  = blockIdx.x * 8 + warp;
    const int b    = row >> 11;
    const int cnt  = g_cnt[row];

    float s[NH];
#pragma unroll
    for (int h = 0; h < NH; h++) s[h] = g_s[row*NH + h];

    for (int q = lane; q < cnt*NH; q += 32) {
        int k = q >> 2, h = q & 3;
        int jr = (b << 11) | g_nbr[(size_t)row*MAXD + k];
        float a = s[h] + g_d[jr*NH + h];
        float e = __expf(a > 0.0f ? a : NEG * a);
        g_w[(size_t)row*MAXD*NH + q] = e;            // coalesced stash
        atomicAdd(&g_denom[jr*NH + h], e);
    }
}

// -------- K3: warp-per-row float4 gather --------
#define OW 8   // rows (warps) per block
__global__ void __launch_bounds__(32*OW, 6) k_out(float4* __restrict__ out,
                                                  const float* __restrict__ bias) {
    __shared__ unsigned short list_s[OW][MAXD];
    __shared__ float w_s[OW][MAXD*NH];     // [k*4+h]
    const int warp = threadIdx.x >> 5, lane = threadIdx.x & 31;
    const int row  = blockIdx.x * OW + warp;
    const int b    = row >> 11;
    const int cnt  = g_cnt[row];           // broadcast load

    unsigned short* list = list_s[warp];
    float*          w    = w_s[warp];

    for (int k = lane; k < cnt; k += 32) list[k] = g_nbr[(size_t)row*MAXD + k];
    __syncwarp();

    // weights: coalesced numerator load + scattered denom divide (exp precomputed)
    for (int q = lane; q < cnt*NH; q += 32) {
        int k = q >> 2, h = q & 3;
        int jr = (b << 11) | list[k];
        w[q] = __fdividef(g_w[(size_t)row*MAXD*NH + q], g_denom[jr*NH + h]);
    }
    __syncwarp();

    const int h4 = (lane >> 3) & 3;        // head for this lane's channel group
    const float4* feat4 = (const float4*)g_feat;
    const size_t bbase = (size_t)(b << 11) * 32;   // float4 units per row

    float4 a0 = {0,0,0,0}, a1 = {0,0,0,0}, a2 = {0,0,0,0}, a3 = {0,0,0,0};
    int k = 0;
    for (; k + 4 <= cnt; k += 4) {
        int j0 = list[k+0], j1 = list[k+1], j2 = list[k+2], j3 = list[k+3];
        float4 f0 = feat4[bbase + (size_t)j0*32 + lane];
        float4 f1 = feat4[bbase + (size_t)j1*32 + lane];
        float4 f2 = feat4[bbase + (size_t)j2*32 + lane];
        float4 f3 = feat4[bbase + (size_t)j3*32 + lane];
        float w0 = w[(k+0)*NH + h4], w1 = w[(k+1)*NH + h4];
        float w2 = w[(k+2)*NH + h4], w3 = w[(k+3)*NH + h4];
        a0.x = fmaf(w0, f0.x, a0.x); a0.y = fmaf(w0, f0.y, a0.y);
        a0.z = fmaf(w0, f0.z, a0.z); a0.w = fmaf(w0, f0.w, a0.w);
        a1.x = fmaf(w1, f1.x, a1.x); a1.y = fmaf(w1, f1.y, a1.y);
        a1.z = fmaf(w1, f1.z, a1.z); a1.w = fmaf(w1, f1.w, a1.w);
        a2.x = fmaf(w2, f2.x, a2.x); a2.y = fmaf(w2, f2.y, a2.y);
        a2.z = fmaf(w2, f2.z, a2.z); a2.w = fmaf(w2, f2.w, a2.w);
        a3.x = fmaf(w3, f3.x, a3.x); a3.y = fmaf(w3, f3.y, a3.y);
        a3.z = fmaf(w3, f3.z, a3.z); a3.w = fmaf(w3, f3.w, a3.w);
    }
    for (; k < cnt; k++) {
        int j = list[k];
        float4 f = feat4[bbase + (size_t)j*32 + lane];
        float wv = w[k*NH + h4];
        a0.x = fmaf(wv, f.x, a0.x); a0.y = fmaf(wv, f.y, a0.y);
        a0.z = fmaf(wv, f.z, a0.z); a0.w = fmaf(wv, f.w, a0.w);
    }

    const float4 bv = ((const float4*)bias)[lane];
    float4 r;
    r.x = (a0.x + a1.x) + (a2.x + a3.x) + bv.x;
    r.y = (a0.y + a1.y) + (a2.y + a3.y) + bv.y;
    r.z = (a0.z + a1.z) + (a2.z + a3.z) + bv.z;
    r.w = (a0.w + a1.w) + (a2.w + a3.w) + bv.w;
    out[(size_t)row*32 + lane] = r;
}

// -------- launch --------
extern "C" void kernel_launch(void* const* d_in, const int* in_sizes, int n_in,
                              void* d_out, int out_size) {
    const float* x    = (const float*)d_in[0];   // [B,N,FIN]
    const float* adj  = (const float*)d_in[1];   // [B,N,N]
    const float* W    = (const float*)d_in[2];   // [FIN,HC]
    const float* asrc = (const float*)d_in[3];   // [H,C]
    const float* adst = (const float*)d_in[4];   // [H,C]
    const float* bias = (const float*)d_in[5];   // [HC]
    float4* out = (float4*)d_out;                // [B,N,HC]

    k_front<<<GEMMB + ROWS, 128>>>(x, W, asrc, adst, (const float4*)adj);
    k_denom<<<ROWS/8, 256>>>();
    k_out  <<<ROWS/OW, 32*OW>>>(out, bias);
}

// round 10
// speedup vs baseline: 1.0159x; 1.0159x over previous
#include <cuda_runtime.h>
#include <cstdint>

// Problem dims (fixed by the reference)
#define NB   4
#define NN   2048
#define FIN  128
#define NH   4
#define NC   32
#define HC   128            // NH*NC
#define ROWS (NB*NN)        // 8192 flattened (b,n)
#define MAXD 128            // neighbor-list capacity per row (avg degree ~21.5)
#define NEG  0.2f
#define GEMMB (ROWS/8)      // 1024 gemm blocks (8 nodes each)

// -------- device scratch (no allocations allowed) --------
__device__ float          g_feat [ROWS*HC];       // x@W (4MB)
__device__ float          g_s    [ROWS*NH];       // a_src logits
__device__ float          g_d    [ROWS*NH];       // a_dst logits
__device__ float          g_denom[ROWS*NH];       // column softmax denominators
__device__ float          g_w    [ROWS*MAXD*NH];  // per-edge exp numerators
__device__ unsigned short g_nbr  [ROWS*MAXD];     // per-row neighbor indices
__device__ int            g_cnt  [ROWS];          // per-row neighbor counts

// packed f32x2 FMA (Blackwell; ptxas never emits it, PTX-only)
__device__ __forceinline__ unsigned long long ffma2(
        unsigned long long a, unsigned long long b, unsigned long long c) {
    unsigned long long d;
    asm("fma.rn.f32x2 %0, %1, %2, %3;" : "=l"(d) : "l"(a), "l"(b), "l"(c));
    return d;
}

// -------- K1: FUSED, INTERLEAVED 1:8  (bx%9==0 -> gemm, else adj-row scan) --------
// GEMM branch is made L1tex-queue-resistant: W is preloaded in 32-wide register
// chunks (batched independent LDGs, one scoreboard wait per chunk) so the scan
// blocks' DRAM flood cannot inflate a per-k dependent-load chain (R8 failure).
__global__ void __launch_bounds__(128) k_front(
        const float*  __restrict__ x,    const float* __restrict__ W,
        const float*  __restrict__ asrc, const float* __restrict__ adst,
        const float4* __restrict__ adj4) {
    const int t  = threadIdx.x;
    const int bx = blockIdx.x;

    if (bx % 9 == 0) {
        // ---------------- GEMM: 8 nodes/block, thread t = output column ----------------
        const int g  = bx / 9;              // 0..GEMMB-1
        const int n0 = g * 8;
        __shared__ __align__(16) float xs[FIN*8];   // [k][m], 4KB

        // fused: zero softmax denominators (first 256 gemm blocks cover 32K floats)
        {
            int z = g * 128 + t;
            if (z < ROWS*NH) g_denom[z] = 0.0f;
        }

        for (int idx = t; idx < 8*FIN; idx += 128) {
            int m = idx >> 7, k = idx & 127;
            xs[k*8 + m] = x[(size_t)(n0 + m)*FIN + k];
        }
        __syncthreads();

        unsigned long long acc2[4] = {0ull, 0ull, 0ull, 0ull};
        const ulonglong2* xv2 = (const ulonglong2*)xs;
#pragma unroll
        for (int kc = 0; kc < 4; kc++) {
            // batched W preload: 32 independent coalesced LDGs, ONE wait
            float wreg[32];
#pragma unroll
            for (int u = 0; u < 32; u++)
                wreg[u] = __ldg(&W[(size_t)(kc*32 + u)*HC + t]);
            // pure-register/LDS compute: per k = 1 pack + 2 LDS.128 + 4 FFMA2
#pragma unroll
            for (int u = 0; u < 32; u++) {
                unsigned long long wv2;
                asm("mov.b64 %0, {%1, %1};" : "=l"(wv2) : "r"(__float_as_uint(wreg[u])));
                const int k = kc*32 + u;
                ulonglong2 p0 = xv2[k*2+0];     // m0..3 (broadcast LDS.128)
                ulonglong2 p1 = xv2[k*2+1];     // m4..7
                acc2[0] = ffma2(p0.x, wv2, acc2[0]);
                acc2[1] = ffma2(p0.y, wv2, acc2[1]);
                acc2[2] = ffma2(p1.x, wv2, acc2[2]);
                acc2[3] = ffma2(p1.y, wv2, acc2[3]);
            }
        }

        float am[8];
#pragma unroll
        for (int p = 0; p < 4; p++) {
            unsigned int lo, hi;
            asm("mov.b64 {%0, %1}, %2;" : "=r"(lo), "=r"(hi) : "l"(acc2[p]));
            am[2*p+0] = __uint_as_float(lo);
            am[2*p+1] = __uint_as_float(hi);
        }

#pragma unroll
        for (int m = 0; m < 8; m++)
            g_feat[(size_t)(n0+m)*HC + t] = am[m];

        // fused attention logits: warp == head h, lane == channel c
        const int h = t >> 5, lane = t & 31;
        const float as = asrc[h*NC + lane];
        const float ad = adst[h*NC + lane];
#pragma unroll
        for (int m = 0; m < 8; m++) {
            float vs = am[m] * as;
            float vd = am[m] * ad;
#pragma unroll
            for (int o = 16; o; o >>= 1) {
                vs += __shfl_xor_sync(0xffffffffu, vs, o);
                vd += __shfl_xor_sync(0xffffffffu, vd, o);
            }
            if (lane == 0) {
                g_s[(n0 + m)*NH + h] = vs;
                g_d[(n0 + m)*NH + h] = vd;
            }
        }
    } else {
        // ---------------- SCAN: one adj row/block, 4 batched LDG.128 per thread ----------------
        __shared__ int cnt_s;
        __shared__ unsigned short list_s[MAXD];
        const int row = bx - bx/9 - 1;      // de-interleaved row id, 0..ROWS-1
        const int i   = row & (NN - 1);

        if (t == 0) cnt_s = 0;

        const float4* base = adj4 + (size_t)row * (NN/4);
        float4 v0 = base[t      ];
        float4 v1 = base[t + 128];
        float4 v2 = base[t + 256];
        float4 v3 = base[t + 384];
        __syncthreads();

        float vals[16] = {v0.x,v0.y,v0.z,v0.w, v1.x,v1.y,v1.z,v1.w,
                          v2.x,v2.y,v2.z,v2.w, v3.x,v3.y,v3.z,v3.w};
#pragma unroll
        for (int u = 0; u < 4; u++) {
#pragma unroll
            for (int c = 0; c < 4; c++) {
                int j = (t + u*128)*4 + c;
                if (vals[u*4+c] != 0.0f || j == i) {   // self-loop always present
                    int p = atomicAdd(&cnt_s, 1);
                    if (p < MAXD) list_s[p] = (unsigned short)j;
                }
            }
        }
        __syncthreads();

        const int cnt = min(cnt_s, MAXD);
        if (t == 0) g_cnt[row] = cnt;
        if (t < cnt) g_nbr[(size_t)row*MAXD + t] = list_s[t];
    }
}

// -------- K2: column softmax denominators + stash per-edge exp numerators --------
__global__ void __launch_bounds__(256) k_denom() {
    const int warp = threadIdx.x >> 5, lane = threadIdx.x & 31;
    const int row  = blockIdx.x * 8 + warp;
    const int b    = row >> 11;
    const int cnt  = g_cnt[row];

    float s[NH];
#pragma unroll
    for (int h = 0; h < NH; h++) s[h] = g_s[row*NH + h];

    for (int q = lane; q < cnt*NH; q += 32) {
        int k = q >> 2, h = q & 3;
        int jr = (b << 11) | g_nbr[(size_t)row*MAXD + k];
        float a = s[h] + g_d[jr*NH + h];
        float e = __expf(a > 0.0f ? a : NEG * a);
        g_w[(size_t)row*MAXD*NH + q] = e;            // coalesced stash
        atomicAdd(&g_denom[jr*NH + h], e);
    }
}

// -------- K3: warp-per-row float4 gather --------
#define OW 8   // rows (warps) per block
__global__ void __launch_bounds__(32*OW, 6) k_out(float4* __restrict__ out,
                                                  const float* __restrict__ bias) {
    __shared__ unsigned short list_s[OW][MAXD];
    __shared__ float w_s[OW][MAXD*NH];     // [k*4+h]
    const int warp = threadIdx.x >> 5, lane = threadIdx.x & 31;
    const int row  = blockIdx.x * OW + warp;
    const int b    = row >> 11;
    const int cnt  = g_cnt[row];           // broadcast load

    unsigned short* list = list_s[warp];
    float*          w    = w_s[warp];

    for (int k = lane; k < cnt; k += 32) list[k] = g_nbr[(size_t)row*MAXD + k];
    __syncwarp();

    // weights: coalesced numerator load + scattered denom divide (exp precomputed)
    for (int q = lane; q < cnt*NH; q += 32) {
        int k = q >> 2, h = q & 3;
        int jr = (b << 11) | list[k];
        w[q] = __fdividef(g_w[(size_t)row*MAXD*NH + q], g_denom[jr*NH + h]);
    }
    __syncwarp();

    const int h4 = (lane >> 3) & 3;        // head for this lane's channel group
    const float4* feat4 = (const float4*)g_feat;
    const size_t bbase = (size_t)(b << 11) * 32;   // float4 units per row

    float4 a0 = {0,0,0,0}, a1 = {0,0,0,0}, a2 = {0,0,0,0}, a3 = {0,0,0,0};
    int k = 0;
    for (; k + 4 <= cnt; k += 4) {
        int j0 = list[k+0], j1 = list[k+1], j2 = list[k+2], j3 = list[k+3];
        float4 f0 = feat4[bbase + (size_t)j0*32 + lane];
        float4 f1 = feat4[bbase + (size_t)j1*32 + lane];
        float4 f2 = feat4[bbase + (size_t)j2*32 + lane];
        float4 f3 = feat4[bbase + (size_t)j3*32 + lane];
        float w0 = w[(k+0)*NH + h4], w1 = w[(k+1)*NH + h4];
        float w2 = w[(k+2)*NH + h4], w3 = w[(k+3)*NH + h4];
        a0.x = fmaf(w0, f0.x, a0.x); a0.y = fmaf(w0, f0.y, a0.y);
        a0.z = fmaf(w0, f0.z, a0.z); a0.w = fmaf(w0, f0.w, a0.w);
        a1.x = fmaf(w1, f1.x, a1.x); a1.y = fmaf(w1, f1.y, a1.y);
        a1.z = fmaf(w1, f1.z, a1.z); a1.w = fmaf(w1, f1.w, a1.w);
        a2.x = fmaf(w2, f2.x, a2.x); a2.y = fmaf(w2, f2.y, a2.y);
        a2.z = fmaf(w2, f2.z, a2.z); a2.w = fmaf(w2, f2.w, a2.w);
        a3.x = fmaf(w3, f3.x, a3.x); a3.y = fmaf(w3, f3.y, a3.y);
        a3.z = fmaf(w3, f3.z, a3.z); a3.w = fmaf(w3, f3.w, a3.w);
    }
    for (; k < cnt; k++) {
        int j = list[k];
        float4 f = feat4[bbase + (size_t)j*32 + lane];
        float wv = w[k*NH + h4];
        a0.x = fmaf(wv, f.x, a0.x); a0.y = fmaf(wv, f.y, a0.y);
        a0.z = fmaf(wv, f.z, a0.z); a0.w = fmaf(wv, f.w, a0.w);
    }

    const float4 bv = ((const float4*)bias)[lane];
    float4 r;
    r.x = (a0.x + a1.x) + (a2.x + a3.x) + bv.x;
    r.y = (a0.y + a1.y) + (a2.y + a3.y) + bv.y;
    r.z = (a0.z + a1.z) + (a2.z + a3.z) + bv.z;
    r.w = (a0.w + a1.w) + (a2.w + a3.w) + bv.w;
    out[(size_t)row*32 + lane] = r;
}

// -------- launch --------
extern "C" void kernel_launch(void* const* d_in, const int* in_sizes, int n_in,
                              void* d_out, int out_size) {
    const float* x    = (const float*)d_in[0];   // [B,N,FIN]
    const float* adj  = (const float*)d_in[1];   // [B,N,N]
    const float* W    = (const float*)d_in[2];   // [FIN,HC]
    const float* asrc = (const float*)d_in[3];   // [H,C]
    const float* adst = (const float*)d_in[4];   // [H,C]
    const float* bias = (const float*)d_in[5];   // [HC]
    float4* out = (float4*)d_out;                // [B,N,HC]

    k_front<<<GEMMB + ROWS, 128>>>(x, W, asrc, adst, (const float4*)adj);
    k_denom<<<ROWS/8, 256>>>();
    k_out  <<<ROWS/OW, 32*OW>>>(out, bias);
}

// round 11
// speedup vs baseline: 1.0986x; 1.0814x over previous
#include <cuda_runtime.h>
#include <cstdint>

// Problem dims (fixed by the reference)
#define NB   4
#define NN   2048
#define FIN  128
#define NH   4
#define NC   32
#define HC   128            // NH*NC
#define ROWS (NB*NN)        // 8192 flattened (b,n)
#define MAXD 128            // neighbor-list capacity per row (avg degree ~21.5)
#define NEG  0.2f

// -------- device scratch (no allocations allowed) --------
__device__ float          g_feat [ROWS*HC];       // x@W (4MB)
__device__ float          g_s    [ROWS*NH];       // a_src logits
__device__ float          g_d    [ROWS*NH];       // a_dst logits
__device__ float          g_denom[ROWS*NH];       // column softmax denominators
__device__ float          g_w    [ROWS*MAXD*NH];  // per-edge exp numerators
__device__ unsigned short g_nbr  [ROWS*MAXD];     // per-row neighbor indices
__device__ int            g_cnt  [ROWS];          // per-row neighbor counts

// packed f32x2 FMA (Blackwell; ptxas never emits it, PTX-only). Bit-exact per lane.
__device__ __forceinline__ unsigned long long ffma2(
        unsigned long long a, unsigned long long b, unsigned long long c) {
    unsigned long long d;
    asm("fma.rn.f32x2 %0, %1, %2, %3;" : "=l"(d) : "l"(a), "l"(b), "l"(c));
    return d;
}

// -------- K1: feat = x @ W (+ logits + denom zeroing), f32x2 mainloop --------
// Standalone launch: no scan co-residents, so the per-k L1-resident W load
// chain is latency-safe. 8 nodes/block, thread t = output column.
__global__ void __launch_bounds__(128) k_gemm(
        const float* __restrict__ x,    const float* __restrict__ W,
        const float* __restrict__ asrc, const float* __restrict__ adst) {
    __shared__ __align__(16) float xs[FIN*8];   // [k][m], 4KB
    const int t  = threadIdx.x;
    const int n0 = blockIdx.x * 8;

    // fused: zero softmax denominators (first 256 blocks cover 32K floats)
    {
        int z = blockIdx.x * 128 + t;
        if (z < ROWS*NH) g_denom[z] = 0.0f;
    }

    for (int idx = t; idx < 8*FIN; idx += 128) {
        int m = idx >> 7, k = idx & 127;
        xs[k*8 + m] = x[(size_t)(n0 + m)*FIN + k];
    }
    __syncthreads();

    // per k: 1 LDG + 1 pack + 2 LDS.128 + 4 FFMA2 (8 MACs)
    unsigned long long acc2[4] = {0ull, 0ull, 0ull, 0ull};
    const ulonglong2* xv2 = (const ulonglong2*)xs;
#pragma unroll 8
    for (int k = 0; k < FIN; k++) {
        float wv = __ldg(&W[(size_t)k*HC + t]);
        unsigned long long wv2;
        asm("mov.b64 %0, {%1, %1};" : "=l"(wv2) : "r"(__float_as_uint(wv)));
        ulonglong2 p0 = xv2[k*2+0];     // m0..3 (broadcast LDS.128)
        ulonglong2 p1 = xv2[k*2+1];     // m4..7
        acc2[0] = ffma2(p0.x, wv2, acc2[0]);
        acc2[1] = ffma2(p0.y, wv2, acc2[1]);
        acc2[2] = ffma2(p1.x, wv2, acc2[2]);
        acc2[3] = ffma2(p1.y, wv2, acc2[3]);
    }

    float am[8];
#pragma unroll
    for (int p = 0; p < 4; p++) {
        unsigned int lo, hi;
        asm("mov.b64 {%0, %1}, %2;" : "=r"(lo), "=r"(hi) : "l"(acc2[p]));
        am[2*p+0] = __uint_as_float(lo);
        am[2*p+1] = __uint_as_float(hi);
    }

#pragma unroll
    for (int m = 0; m < 8; m++)
        g_feat[(size_t)(n0+m)*HC + t] = am[m];

    // fused attention logits: warp == head h, lane == channel c
    const int h = t >> 5, lane = t & 31;
    const float as = asrc[h*NC + lane];
    const float ad = adst[h*NC + lane];
#pragma unroll
    for (int m = 0; m < 8; m++) {
        float vs = am[m] * as;
        float vd = am[m] * ad;
#pragma unroll
        for (int o = 16; o; o >>= 1) {
            vs += __shfl_xor_sync(0xffffffffu, vs, o);
            vd += __shfl_xor_sync(0xffffffffu, vd, o);
        }
        if (lane == 0) {
            g_s[(n0 + m)*NH + h] = vs;
            g_d[(n0 + m)*NH + h] = vd;
        }
    }
}

// -------- K2: FUSED scan + exp + denom  (runs after gemm; list still in smem) --------
// One adj row per block. Batched LDG.128 covers the row; then per-(edge,head)
// exp is computed from the smem list, stashed to g_w, and atomically summed
// into the column denominators. The ALU tail hides under the scan's DRAM time.
__global__ void __launch_bounds__(128) k_edge(const float4* __restrict__ adj4) {
    __shared__ int cnt_s;
    __shared__ unsigned short list_s[MAXD];
    __shared__ float s_sh[NH];
    const int row = blockIdx.x;           // flattened (b,i)
    const int b   = row >> 11;
    const int i   = row & (NN - 1);
    const int t   = threadIdx.x;

    if (t == 0) cnt_s = 0;
    if (t < NH) s_sh[t] = g_s[row*NH + t];

    const float4* base = adj4 + (size_t)row * (NN/4);
    float4 v0 = base[t      ];
    float4 v1 = base[t + 128];
    float4 v2 = base[t + 256];
    float4 v3 = base[t + 384];
    __syncthreads();

    float vals[16] = {v0.x,v0.y,v0.z,v0.w, v1.x,v1.y,v1.z,v1.w,
                      v2.x,v2.y,v2.z,v2.w, v3.x,v3.y,v3.z,v3.w};
#pragma unroll
    for (int u = 0; u < 4; u++) {
#pragma unroll
        for (int c = 0; c < 4; c++) {
            int j = (t + u*128)*4 + c;
            if (vals[u*4+c] != 0.0f || j == i) {   // self-loop always present
                int p = atomicAdd(&cnt_s, 1);
                if (p < MAXD) list_s[p] = (unsigned short)j;
            }
        }
    }
    __syncthreads();

    const int cnt = min(cnt_s, MAXD);
    if (t == 0) g_cnt[row] = cnt;
    if (t < cnt) g_nbr[(size_t)row*MAXD + t] = list_s[t];

    // fused denominator pass (list is hot in smem; s in smem; d scattered L2)
    for (int q = t; q < cnt*NH; q += 128) {
        int k = q >> 2, h = q & 3;
        int jr = (b << 11) | list_s[k];
        float a = s_sh[h] + g_d[jr*NH + h];
        float e = __expf(a > 0.0f ? a : NEG * a);
        g_w[(size_t)row*MAXD*NH + q] = e;            // coalesced stash
        atomicAdd(&g_denom[jr*NH + h], e);
    }
}

// -------- K3: warp-per-row float4 gather --------
#define OW 8   // rows (warps) per block
__global__ void __launch_bounds__(32*OW, 6) k_out(float4* __restrict__ out,
                                                  const float* __restrict__ bias) {
    __shared__ unsigned short list_s[OW][MAXD];
    __shared__ float w_s[OW][MAXD*NH];     // [k*4+h]
    const int warp = threadIdx.x >> 5, lane = threadIdx.x & 31;
    const int row  = blockIdx.x * OW + warp;
    const int b    = row >> 11;
    const int cnt  = g_cnt[row];           // broadcast load

    unsigned short* list = list_s[warp];
    float*          w    = w_s[warp];

    for (int k = lane; k < cnt; k += 32) list[k] = g_nbr[(size_t)row*MAXD + k];
    __syncwarp();

    // weights: coalesced numerator load + scattered denom divide (exp precomputed)
    for (int q = lane; q < cnt*NH; q += 32) {
        int k = q >> 2, h = q & 3;
        int jr = (b << 11) | list[k];
        w[q] = __fdividef(g_w[(size_t)row*MAXD*NH + q], g_denom[jr*NH + h]);
    }
    __syncwarp();

    const int h4 = (lane >> 3) & 3;        // head for this lane's channel group
    const float4* feat4 = (const float4*)g_feat;
    const size_t bbase = (size_t)(b << 11) * 32;   // float4 units per row

    float4 a0 = {0,0,0,0}, a1 = {0,0,0,0}, a2 = {0,0,0,0}, a3 = {0,0,0,0};
    int k = 0;
    for (; k + 4 <= cnt; k += 4) {
        int j0 = list[k+0], j1 = list[k+1], j2 = list[k+2], j3 = list[k+3];
        float4 f0 = feat4[bbase + (size_t)j0*32 + lane];
        float4 f1 = feat4[bbase + (size_t)j1*32 + lane];
        float4 f2 = feat4[bbase + (size_t)j2*32 + lane];
        float4 f3 = feat4[bbase + (size_t)j3*32 + lane];
        float w0 = w[(k+0)*NH + h4], w1 = w[(k+1)*NH + h4];
        float w2 = w[(k+2)*NH + h4], w3 = w[(k+3)*NH + h4];
        a0.x = fmaf(w0, f0.x, a0.x); a0.y = fmaf(w0, f0.y, a0.y);
        a0.z = fmaf(w0, f0.z, a0.z); a0.w = fmaf(w0, f0.w, a0.w);
        a1.x = fmaf(w1, f1.x, a1.x); a1.y = fmaf(w1, f1.y, a1.y);
        a1.z = fmaf(w1, f1.z, a1.z); a1.w = fmaf(w1, f1.w, a1.w);
        a2.x = fmaf(w2, f2.x, a2.x); a2.y = fmaf(w2, f2.y, a2.y);
        a2.z = fmaf(w2, f2.z, a2.z); a2.w = fmaf(w2, f2.w, a2.w);
        a3.x = fmaf(w3, f3.x, a3.x); a3.y = fmaf(w3, f3.y, a3.y);
        a3.z = fmaf(w3, f3.z, a3.z); a3.w = fmaf(w3, f3.w, a3.w);
    }
    for (; k < cnt; k++) {
        int j = list[k];
        float4 f = feat4[bbase + (size_t)j*32 + lane];
        float wv = w[k*NH + h4];
        a0.x = fmaf(wv, f.x, a0.x); a0.y = fmaf(wv, f.y, a0.y);
        a0.z = fmaf(wv, f.z, a0.z); a0.w = fmaf(wv, f.w, a0.w);
    }

    const float4 bv = ((const float4*)bias)[lane];
    float4 r;
    r.x = (a0.x + a1.x) + (a2.x + a3.x) + bv.x;
    r.y = (a0.y + a1.y) + (a2.y + a3.y) + bv.y;
    r.z = (a0.z + a1.z) + (a2.z + a3.z) + bv.z;
    r.w = (a0.w + a1.w) + (a2.w + a3.w) + bv.w;
    out[(size_t)row*32 + lane] = r;
}

// -------- launch --------
extern "C" void kernel_launch(void* const* d_in, const int* in_sizes, int n_in,
                              void* d_out, int out_size) {
    const float* x    = (const float*)d_in[0];   // [B,N,FIN]
    const float* adj  = (const float*)d_in[1];   // [B,N,N]
    const float* W    = (const float*)d_in[2];   // [FIN,HC]
    const float* asrc = (const float*)d_in[3];   // [H,C]
    const float* adst = (const float*)d_in[4];   // [H,C]
    const float* bias = (const float*)d_in[5];   // [HC]
    float4* out = (float4*)d_out;                // [B,N,HC]

    k_gemm<<<ROWS/8, 128>>>(x, W, asrc, adst);   // also zeros g_denom
    k_edge<<<ROWS, 128>>>((const float4*)adj);   // scan + exp + denom fused
    k_out <<<ROWS/OW, 32*OW>>>(out, bias);
}